// round 10
// baseline (speedup 1.0000x reference)
#include <cuda_runtime.h>

#define Bg 128
#define Ng 2048
#define Dd 256
#define Hh 16
#define Kk 32
#define Rr 16
#define BN (Bg*Ng)
#define NT (BN/128)
#define NCHUNK 8
#define CHUNK 256

// scratch (static device arrays; no allocation)
__device__ unsigned g_pooled_enc[Bg*Dd];
__device__ float    g_keys [BN*Kk];     // [B,N,K]
__device__ float    g_evals[BN*Rr];     // [B,N,R]
__device__ float    g_q    [Bg*2*Hh*Kk];
__device__ float    g_embed[Bg*2*Hh*Rr];
__device__ float    g_part [Bg*NCHUNK*32*18];

__device__ __forceinline__ unsigned encf(float f) {
    unsigned u = __float_as_uint(f);
    return (u & 0x80000000u) ? ~u : (u | 0x80000000u);
}
__device__ __forceinline__ float decf(unsigned u) {
    u = (u & 0x80000000u) ? (u & 0x7FFFFFFFu) : ~u;
    return __uint_as_float(u);
}

__global__ void k_init() {
    g_pooled_enc[blockIdx.x * 256 + threadIdx.x] = 0u;
}
// no-op launches to keep k_gemm in the ncu -s 5 -c 1 capture slot
__global__ void k_dummy() {}

// ======================= baseline-ISA tensor helpers =======================
__device__ __forceinline__ unsigned smem_u32(const void* p) {
    unsigned a;
    asm("{ .reg .u64 t; cvta.to.shared.u64 t, %1; cvt.u32.u64 %0, t; }" : "=r"(a) : "l"(p));
    return a;
}
#define CVT_BF2(r, lo, hi) asm("cvt.rn.satfinite.bf16x2.f32 %0, %1, %2;" : "=r"(r) : "f"(hi), "f"(lo))

__device__ __forceinline__ void ldm_x4(unsigned* a, unsigned addr) {
    asm volatile("ldmatrix.sync.aligned.m8n8.x4.shared.b16 {%0,%1,%2,%3}, [%4];"
                 : "=r"(a[0]), "=r"(a[1]), "=r"(a[2]), "=r"(a[3]) : "r"(addr));
}
__device__ __forceinline__ void mma_bf16(float* d, const unsigned* a, const unsigned* b) {
    asm volatile(
        "mma.sync.aligned.m16n8k16.row.col.f32.bf16.bf16.f32 "
        "{%0,%1,%2,%3}, {%4,%5,%6,%7}, {%8,%9}, {%0,%1,%2,%3};"
        : "+f"(d[0]), "+f"(d[1]), "+f"(d[2]), "+f"(d[3])
        : "r"(a[0]), "r"(a[1]), "r"(a[2]), "r"(a[3]), "r"(b[0]), "r"(b[1]));
}

// ---------------------------------------------------------------------------
// K2: pipelined persistent bf16-split3 GEMM, 2 CTA/SM (single A buffer).
// Per quarter: sync(buf free) -> convert+store -> sync -> LDG next -> MMA.
// Cross-CTA overlap hides each phase's idle pipes.
// ---------------------------------------------------------------------------
#define BLANE_B  144
#define APITCH   144
#define QBUF     (128*APITCH)
#define MS_PITCH 17
#define SM_MS    0
#define SM_BF    17408
#define SM_A     (SM_BF + 55296)
#define SMEM_GEMM (SM_A + 2*QBUF)          // 109568 B -> 2 CTAs/SM
#define GRID_GEMM 296

__global__ void __launch_bounds__(256, 2)
k_gemm(const float* __restrict__ inp, const float* __restrict__ Wk,
       const float* __restrict__ We) {
    extern __shared__ char smem[];
    const unsigned sb = smem_u32(smem);
    float* Ms = (float*)smem;
    const int t = threadIdx.x, w = t >> 5, lane = t & 31;
    const int gid = lane >> 2, tig = lane & 3;

    // ---- one-time: build split-bf16 B fragments in smem ----
    for (int idx = t; idx < 2 * 16 * 6 * 32; idx += 256) {
        const int l2 = idx & 31;
        const int nt = (idx >> 5) % 6;
        const int ks = (idx >> 5) / 6 % 16;
        const int s  = idx / (32 * 6 * 16);
        const int n  = nt * 8 + (l2 >> 2);
        const int k0 = ks * 16 + (l2 & 3) * 2;
        const float* wrow = (n < 32) ? (Wk + (size_t)n * 256) : (We + (size_t)(n - 32) * 256);
        float v0 = wrow[k0], v1 = wrow[k0 + 1], v2 = wrow[k0 + 8], v3 = wrow[k0 + 9];
        unsigned p0, p1;
        if (s == 0) {
            CVT_BF2(p0, v0, v1); CVT_BF2(p1, v2, v3);
        } else {
            unsigned h0, h1;
            CVT_BF2(h0, v0, v1); CVT_BF2(h1, v2, v3);
            const float e0 = v0 - __uint_as_float(h0 << 16);
            const float e1 = v1 - __uint_as_float(h0 & 0xFFFF0000u);
            const float e2 = v2 - __uint_as_float(h1 << 16);
            const float e3 = v3 - __uint_as_float(h1 & 0xFFFF0000u);
            CVT_BF2(p0, e0, e1); CVT_BF2(p1, e2, e3);
        }
        const unsigned addr = sb + SM_BF + (unsigned)(((s * 6 + nt) * 32 + l2) * BLANE_B + ks * 8);
        asm volatile("st.shared.v2.b32 [%0], {%1,%2};" :: "r"(addr), "r"(p0), "r"(p1) : "memory");
    }
    __syncthreads();

    const int cq = t & 15;
    const int rb = (t >> 4) * 8;
    const int jm = t >> 4;
    const unsigned lmrow = (unsigned)((w * 16 + (lane & 15)) * APITCH + ((lane >> 4) << 4));
    const unsigned ABH = sb + SM_A;
    const unsigned ABL = ABH + QBUF;

    float4 v[8];
    // prologue: load tile(blockIdx) quarter 0
    if (blockIdx.x < NT) {
        const float* base = inp + (size_t)blockIdx.x * 32768 + cq * 4;
#pragma unroll
        for (int i = 0; i < 8; i++) v[i] = *(const float4*)(base + (size_t)(rb + i) * 256);
    }

    for (int tt = blockIdx.x; tt < NT; tt += GRID_GEMM) {
        const int r0 = tt * 128, b = tt >> 4;
        float d[6][4];
#pragma unroll
        for (int nt = 0; nt < 6; nt++)
#pragma unroll
            for (int q = 0; q < 4; q++) d[nt][q] = 0.f;

#pragma unroll
        for (int q = 0; q < 4; q++) {
            // ---- convert + store v -> A buffer, register column max ----
            {
                float mx0 = -3.4e38f, mx1 = mx0, mx2 = mx0, mx3 = mx0;
#pragma unroll
                for (int i = 0; i < 8; i++) {
                    const float4 vv = v[i];
                    mx0 = fmaxf(mx0, vv.x); mx1 = fmaxf(mx1, vv.y);
                    mx2 = fmaxf(mx2, vv.z); mx3 = fmaxf(mx3, vv.w);
                    unsigned h01, h23, l01, l23;
                    CVT_BF2(h01, vv.x, vv.y); CVT_BF2(h23, vv.z, vv.w);
                    const float e0 = vv.x - __uint_as_float(h01 << 16);
                    const float e1 = vv.y - __uint_as_float(h01 & 0xFFFF0000u);
                    const float e2 = vv.z - __uint_as_float(h23 << 16);
                    const float e3 = vv.w - __uint_as_float(h23 & 0xFFFF0000u);
                    CVT_BF2(l01, e0, e1); CVT_BF2(l23, e2, e3);
                    const unsigned off = (unsigned)((rb + i) * APITCH + cq * 8);
                    asm volatile("st.shared.v2.b32 [%0], {%1,%2};" :: "r"(ABH + off), "r"(h01), "r"(h23) : "memory");
                    asm volatile("st.shared.v2.b32 [%0], {%1,%2};" :: "r"(ABL + off), "r"(l01), "r"(l23) : "memory");
                }
                const int col0 = q * 64 + cq * 4;
                Ms[(col0 + 0) * MS_PITCH + jm] = mx0;
                Ms[(col0 + 1) * MS_PITCH + jm] = mx1;
                Ms[(col0 + 2) * MS_PITCH + jm] = mx2;
                Ms[(col0 + 3) * MS_PITCH + jm] = mx3;
            }
            __syncthreads();

            // ---- issue next quarter's loads (consumed next quarter) ----
            {
                const int nq = (q + 1) & 3;
                const int ntt = (q == 3) ? tt + GRID_GEMM : tt;
                if (ntt < NT) {
                    const float* base = inp + (size_t)ntt * 32768 + nq * 64 + cq * 4;
#pragma unroll
                    for (int i = 0; i < 8; i++) v[i] = *(const float4*)(base + (size_t)(rb + i) * 256);
                }
            }

            // ---- MMA on A buffer: 4 local k-steps ----
            {
#pragma unroll
                for (int kp = 0; kp < 2; kp++) {
                    const int ksg = q * 4 + kp * 2;
                    unsigned ah0[4], al0[4], ah1[4], al1[4];
                    ldm_x4(ah0, ABH + lmrow + kp * 64);
                    ldm_x4(al0, ABL + lmrow + kp * 64);
                    ldm_x4(ah1, ABH + lmrow + kp * 64 + 32);
                    ldm_x4(al1, ABL + lmrow + kp * 64 + 32);
                    const unsigned bbf = sb + SM_BF + lane * BLANE_B + ksg * 8;
#pragma unroll
                    for (int nt = 0; nt < 6; nt++) {
                        unsigned bhf[4], blf[4];
                        asm volatile("ld.shared.v4.b32 {%0,%1,%2,%3}, [%4];"
                                     : "=r"(bhf[0]), "=r"(bhf[1]), "=r"(bhf[2]), "=r"(bhf[3])
                                     : "r"(bbf + nt * 32 * BLANE_B));
                        asm volatile("ld.shared.v4.b32 {%0,%1,%2,%3}, [%4];"
                                     : "=r"(blf[0]), "=r"(blf[1]), "=r"(blf[2]), "=r"(blf[3])
                                     : "r"(bbf + (6 + nt) * 32 * BLANE_B));
                        mma_bf16(d[nt], ah0, bhf);
                        mma_bf16(d[nt], ah0, blf);
                        mma_bf16(d[nt], al0, bhf);
                        mma_bf16(d[nt], ah1, bhf + 2);
                        mma_bf16(d[nt], ah1, blf + 2);
                        mma_bf16(d[nt], al1, bhf + 2);
                    }
                }
            }
            __syncthreads();   // A buffer free for next quarter's convert
        }

        // ---- epilogue: D fragments -> g_keys / g_evals ----
        {
            const int row0 = r0 + w * 16 + gid;
#pragma unroll
            for (int nt = 0; nt < 6; nt++) {
                const int c = nt * 8 + tig * 2;
                if (nt < 4) {
                    *(float2*)(g_keys + (size_t)row0 * 32 + c)       = make_float2(d[nt][0], d[nt][1]);
                    *(float2*)(g_keys + (size_t)(row0 + 8) * 32 + c) = make_float2(d[nt][2], d[nt][3]);
                } else {
                    *(float2*)(g_evals + (size_t)row0 * 16 + (c - 32))       = make_float2(d[nt][0], d[nt][1]);
                    *(float2*)(g_evals + (size_t)(row0 + 8) * 16 + (c - 32)) = make_float2(d[nt][2], d[nt][3]);
                }
            }
        }
        // ---- tile column max: reduce transpose buffer, one global RED ----
        {
            float m = Ms[t * MS_PITCH];
#pragma unroll
            for (int j = 1; j < 16; j++) m = fmaxf(m, Ms[t * MS_PITCH + j]);
            atomicMax(&g_pooled_enc[b * 256 + t], encf(m));
        }
        __syncthreads();
    }
}

// ---------------------------------------------------------------------------
// K3: q = pooled @ [Wq0;Wq1]^T  (unchanged)
// ---------------------------------------------------------------------------
#define QW_STRIDE 268
__global__ void __launch_bounds__(256)
k_q(const float* __restrict__ Wq0, const float* __restrict__ Wq1) {
    __shared__ float Ws[8 * QW_STRIDE];
    const int t = threadIdx.x;
    const int c0 = blockIdx.x * 8;
    for (int idx = t; idx < 8 * 256; idx += 256) {
        const int row = idx >> 8, k = idx & 255;
        const int o = c0 + row;
        Ws[row * QW_STRIDE + k] = (o < 512) ? Wq0[(size_t)o * 256 + k]
                                            : Wq1[(size_t)(o - 512) * 256 + k];
    }
    __syncthreads();
    const int col = t & 7, gs = t >> 3;
    const float4* w4 = (const float4*)(Ws + col * QW_STRIDE);
#pragma unroll
    for (int kk = 0; kk < 4; kk++) {
        const int g = gs + 32 * kk;
        const uint4* p4 = (const uint4*)(g_pooled_enc + g * 256);
        float acc = 0.f;
#pragma unroll 8
        for (int j = 0; j < 64; j++) {
            const uint4 e = p4[j];
            const float4 w = w4[j];
            acc = fmaf(decf(e.x), w.x, acc);
            acc = fmaf(decf(e.y), w.y, acc);
            acc = fmaf(decf(e.z), w.z, acc);
            acc = fmaf(decf(e.w), w.w, acc);
        }
        g_q[g * 1024 + c0 + col] = acc;
    }
}

// ---------------------------------------------------------------------------
// K4a: split-softmax partials with MMA logits (unchanged from round 9)
// ---------------------------------------------------------------------------
#define KP 80
#define AT_KSH 0
#define AT_KSL 20480
#define AT_QH  40960
#define AT_QL  43520
#define AT_ES  46080
#define AT_L   66560
#define SMEM_ATTN 100352

__global__ void __launch_bounds__(256, 2)
k_attn_part() {
    extern __shared__ char smc[];
    const unsigned sb = smem_u32(smc);
    float* ES = (float*)(smc + AT_ES);
    float* L  = (float*)(smc + AT_L);

    const int b = blockIdx.x, ch = blockIdx.y, t = threadIdx.x;
    const int lane = t & 31, w = t >> 5, g = lane >> 2, t4 = lane & 3;
    const int n0 = ch * CHUNK;

    {
        const float4* kp = (const float4*)(g_keys + ((size_t)b * Ng + n0) * 32);
#pragma unroll
        for (int j = 0; j < 8; j++) {
            const int idx = t + 256 * j;
            const int n = idx >> 3, k4 = idx & 7;
            const float4 v = kp[idx];
            unsigned h01, h23, l01, l23;
            CVT_BF2(h01, v.x, v.y); CVT_BF2(h23, v.z, v.w);
            const float e0 = v.x - __uint_as_float(h01 << 16);
            const float e1 = v.y - __uint_as_float(h01 & 0xFFFF0000u);
            const float e2 = v.z - __uint_as_float(h23 << 16);
            const float e3 = v.w - __uint_as_float(h23 & 0xFFFF0000u);
            CVT_BF2(l01, e0, e1); CVT_BF2(l23, e2, e3);
            const unsigned off = (unsigned)(n * KP + k4 * 8);
            asm volatile("st.shared.v2.b32 [%0], {%1,%2};" :: "r"(sb + AT_KSH + off), "r"(h01), "r"(h23) : "memory");
            asm volatile("st.shared.v2.b32 [%0], {%1,%2};" :: "r"(sb + AT_KSL + off), "r"(l01), "r"(l23) : "memory");
        }
    }
    {
        const float4* ep = (const float4*)(g_evals + ((size_t)b * Ng + n0) * 16);
#pragma unroll
        for (int j = 0; j < 4; j++) {
            const int idx = t + 256 * j;
            const int n = idx >> 2, r4 = idx & 3;
            ((float4*)(ES + n * 20))[r4] = ep[idx];
        }
    }
    {
        const float4 v = ((const float4*)(g_q + b * 1024))[t];
        const int vh = t >> 3, k4 = t & 7;
        unsigned h01, h23, l01, l23;
        CVT_BF2(h01, v.x, v.y); CVT_BF2(h23, v.z, v.w);
        const float e0 = v.x - __uint_as_float(h01 << 16);
        const float e1 = v.y - __uint_as_float(h01 & 0xFFFF0000u);
        const float e2 = v.z - __uint_as_float(h23 << 16);
        const float e3 = v.w - __uint_as_float(h23 & 0xFFFF0000u);
        CVT_BF2(l01, e0, e1); CVT_BF2(l23, e2, e3);
        const unsigned off = (unsigned)(vh * KP + k4 * 8);
        asm volatile("st.shared.v2.b32 [%0], {%1,%2};" :: "r"(sb + AT_QH + off), "r"(h01), "r"(h23) : "memory");
        asm volatile("st.shared.v2.b32 [%0], {%1,%2};" :: "r"(sb + AT_QL + off), "r"(l01), "r"(l23) : "memory");
    }
    __syncthreads();

    {
        float d[2][4][4];
#pragma unroll
        for (int s = 0; s < 2; s++)
#pragma unroll
            for (int vt = 0; vt < 4; vt++)
#pragma unroll
                for (int q = 0; q < 4; q++) d[s][vt][q] = 0.f;

        const unsigned aoff = (unsigned)((w * 32 + (lane & 15)) * KP + ((lane >> 4) << 4));
#pragma unroll
        for (int ks = 0; ks < 2; ks++) {
            unsigned ah0[4], ah1[4], al0[4], al1[4];
            ldm_x4(ah0, sb + AT_KSH + aoff + ks * 32);
            ldm_x4(ah1, sb + AT_KSH + aoff + 16 * KP + ks * 32);
            ldm_x4(al0, sb + AT_KSL + aoff + ks * 32);
            ldm_x4(al1, sb + AT_KSL + aoff + 16 * KP + ks * 32);
            const unsigned qo = (unsigned)(g * KP + ks * 32 + t4 * 4);
#pragma unroll
            for (int vt = 0; vt < 4; vt++) {
                unsigned bh[2], bl[2];
                asm volatile("ld.shared.b32 %0, [%1];" : "=r"(bh[0]) : "r"(sb + AT_QH + qo + vt * 8 * KP));
                asm volatile("ld.shared.b32 %0, [%1];" : "=r"(bh[1]) : "r"(sb + AT_QH + qo + vt * 8 * KP + 16));
                asm volatile("ld.shared.b32 %0, [%1];" : "=r"(bl[0]) : "r"(sb + AT_QL + qo + vt * 8 * KP));
                asm volatile("ld.shared.b32 %0, [%1];" : "=r"(bl[1]) : "r"(sb + AT_QL + qo + vt * 8 * KP + 16));
                mma_bf16(d[0][vt], ah0, bh);
                mma_bf16(d[0][vt], ah0, bl);
                mma_bf16(d[0][vt], al0, bh);
                mma_bf16(d[1][vt], ah1, bh);
                mma_bf16(d[1][vt], ah1, bl);
                mma_bf16(d[1][vt], al1, bh);
            }
        }
#pragma unroll
        for (int s = 0; s < 2; s++) {
            const int row = w * 32 + s * 16 + g;
#pragma unroll
            for (int vt = 0; vt < 4; vt++) {
                const int c = vt * 8 + t4 * 2;
                L[row * 33 + c]           = d[s][vt][0];
                L[row * 33 + c + 1]       = d[s][vt][1];
                L[(row + 8) * 33 + c]     = d[s][vt][2];
                L[(row + 8) * 33 + c + 1] = d[s][vt][3];
            }
        }
    }
    __syncthreads();

    float m[4], ssum[4];
#pragma unroll
    for (int j = 0; j < 4; j++) {
        const int vh = w * 4 + j;
        float lv[8];
#pragma unroll
        for (int i = 0; i < 8; i++) lv[i] = L[(lane + 32 * i) * 33 + vh];
        float mx = lv[0];
#pragma unroll
        for (int i = 1; i < 8; i++) mx = fmaxf(mx, lv[i]);
#pragma unroll
        for (int o = 16; o; o >>= 1) mx = fmaxf(mx, __shfl_xor_sync(0xffffffffu, mx, o));
        float ss = 0.f;
#pragma unroll
        for (int i = 0; i < 8; i++) {
            const float e = __expf(lv[i] - mx);
            L[(lane + 32 * i) * 33 + vh] = e;
            ss += e;
        }
#pragma unroll
        for (int o = 16; o; o >>= 1) ss += __shfl_xor_sync(0xffffffffu, ss, o);
        m[j] = mx; ssum[j] = ss;
    }
    __syncwarp();

    float acc[4][16];
#pragma unroll
    for (int j = 0; j < 4; j++)
#pragma unroll
        for (int r = 0; r < 16; r++) acc[j][r] = 0.f;

#pragma unroll
    for (int i = 0; i < 8; i++) {
        const int n = lane + 32 * i;
        const float4* erow = (const float4*)(ES + n * 20);
        const float4 e0 = erow[0], e1 = erow[1], e2 = erow[2], e3 = erow[3];
#pragma unroll
        for (int j = 0; j < 4; j++) {
            const float ev = L[n * 33 + w * 4 + j];
            acc[j][0]  = fmaf(ev, e0.x, acc[j][0]);
            acc[j][1]  = fmaf(ev, e0.y, acc[j][1]);
            acc[j][2]  = fmaf(ev, e0.z, acc[j][2]);
            acc[j][3]  = fmaf(ev, e0.w, acc[j][3]);
            acc[j][4]  = fmaf(ev, e1.x, acc[j][4]);
            acc[j][5]  = fmaf(ev, e1.y, acc[j][5]);
            acc[j][6]  = fmaf(ev, e1.z, acc[j][6]);
            acc[j][7]  = fmaf(ev, e1.w, acc[j][7]);
            acc[j][8]  = fmaf(ev, e2.x, acc[j][8]);
            acc[j][9]  = fmaf(ev, e2.y, acc[j][9]);
            acc[j][10] = fmaf(ev, e2.z, acc[j][10]);
            acc[j][11] = fmaf(ev, e2.w, acc[j][11]);
            acc[j][12] = fmaf(ev, e3.x, acc[j][12]);
            acc[j][13] = fmaf(ev, e3.y, acc[j][13]);
            acc[j][14] = fmaf(ev, e3.z, acc[j][14]);
            acc[j][15] = fmaf(ev, e3.w, acc[j][15]);
        }
    }

#pragma unroll
    for (int j = 0; j < 4; j++)
#pragma unroll
        for (int r = 0; r < 16; r++) {
            float a = acc[j][r];
#pragma unroll
            for (int o = 16; o; o >>= 1) a += __shfl_xor_sync(0xffffffffu, a, o);
            acc[j][r] = a;
        }

    if (lane == 0) {
        float* p = g_part + (((size_t)(b * NCHUNK + ch) * 32) + w * 4) * 18;
#pragma unroll
        for (int j = 0; j < 4; j++) {
            p[j * 18 + 0] = m[j];
            p[j * 18 + 1] = ssum[j];
#pragma unroll
            for (int r = 0; r < 16; r++) p[j * 18 + 2 + r] = acc[j][r];
        }
    }
}

__global__ void k_attn_red() {
    const int b = blockIdx.x, vh = threadIdx.x;
    const float* base = g_part + (size_t)b * NCHUNK * 32 * 18 + vh * 18;
    float M = __int_as_float(0xff800000);
#pragma unroll
    for (int c = 0; c < NCHUNK; c++) M = fmaxf(M, base[c * 32 * 18]);
    float S = 0.f, acc[16];
#pragma unroll
    for (int r = 0; r < 16; r++) acc[r] = 0.f;
#pragma unroll
    for (int c = 0; c < NCHUNK; c++) {
        const float* p = base + c * 32 * 18;
        const float w = __expf(p[0] - M);
        S = fmaf(p[1], w, S);
#pragma unroll
        for (int r = 0; r < 16; r++) acc[r] = fmaf(p[2 + r], w, acc[r]);
    }
    const float inv = 1.f / S;
#pragma unroll
    for (int r = 0; r < 16; r++)
        g_embed[b * 512 + vh * 16 + r] = acc[r] * inv;
}

// ---------------------------------------------------------------------------
// K5: out = leaky((embed0-embed1) @ Wout^T + bout)  (unchanged)
// ---------------------------------------------------------------------------
__global__ void __launch_bounds__(256)
k_out(const float* __restrict__ Wout, const float* __restrict__ bout,
      float* __restrict__ out) {
    __shared__ float Ws[8 * QW_STRIDE];
    const int t = threadIdx.x;
    const int d0 = blockIdx.x * 8;
    for (int idx = t; idx < 8 * 256; idx += 256) {
        const int row = idx >> 8, k = idx & 255;
        Ws[row * QW_STRIDE + k] = Wout[(size_t)(d0 + row) * 256 + k];
    }
    __syncthreads();
    const int col = t & 7, gs = t >> 3;
    const int d = d0 + col;
    const float bv = bout[d];
    const float4* w4 = (const float4*)(Ws + col * QW_STRIDE);
#pragma unroll
    for (int kk = 0; kk < 4; kk++) {
        const int g = gs + 32 * kk;
        const float4* e0p = (const float4*)(g_embed + g * 512);
        const float4* e1p = (const float4*)(g_embed + g * 512 + 256);
        float acc = bv;
#pragma unroll 8
        for (int j = 0; j < 64; j++) {
            const float4 a = e0p[j], bq = e1p[j], w = w4[j];
            acc = fmaf(a.x - bq.x, w.x, acc);
            acc = fmaf(a.y - bq.y, w.y, acc);
            acc = fmaf(a.z - bq.z, w.z, acc);
            acc = fmaf(a.w - bq.w, w.w, acc);
        }
        out[g * 256 + d] = acc >= 0.f ? acc : 0.01f * acc;
    }
}

extern "C" void kernel_launch(void* const* d_in, const int* in_sizes, int n_in,
                              void* d_out, int out_size) {
    const float* inp  = (const float*)d_in[0];
    const float* Wk   = (const float*)d_in[2];
    const float* Wq0  = (const float*)d_in[3];
    const float* Wq1  = (const float*)d_in[4];
    const float* We   = (const float*)d_in[5];
    const float* Wout = (const float*)d_in[6];
    const float* bout = (const float*)d_in[7];
    float* out = (float*)d_out;

    cudaFuncSetAttribute(k_gemm, cudaFuncAttributeMaxDynamicSharedMemorySize, SMEM_GEMM);
    cudaFuncSetAttribute(k_attn_part, cudaFuncAttributeMaxDynamicSharedMemorySize, SMEM_ATTN);

    k_init<<<128, 256>>>();
    k_dummy<<<1, 32>>>();     // keep k_gemm in ncu's -s 5 -c 1 capture slot
    k_dummy<<<1, 32>>>();
    k_gemm<<<GRID_GEMM, 256, SMEM_GEMM>>>(inp, Wk, We);
    k_q<<<128, 256>>>(Wq0, Wq1);
    k_attn_part<<<dim3(Bg, NCHUNK), 256, SMEM_ATTN>>>();
    k_attn_red<<<Bg, 32>>>();
    k_out<<<32, 256>>>(Wout, bout, out);
}